// round 8
// baseline (speedup 1.0000x reference)
#include <cuda_runtime.h>
#include <math.h>

#define LDIM 32
#define HDIM 64

typedef unsigned long long ull;

__device__ __forceinline__ ull pack2(float lo, float hi) {
    ull r; asm("mov.b64 %0, {%1, %2};" : "=l"(r) : "f"(lo), "f"(hi)); return r;
}
__device__ __forceinline__ float2 unpack2(ull v) {
    float2 r; asm("mov.b64 {%0, %1}, %2;" : "=f"(r.x), "=f"(r.y) : "l"(v)); return r;
}
#define FMA2(d, a, b, c) \
    asm("fma.rn.f32x2 %0, %1, %2, %3;" : "=l"(d) : "l"(a), "l"(b), "l"(c))

// TWO samples per warp; thread t owns channels {t, t+32} of both samples and
// the 128 packed Wc weight registers are SHARED between the two chains.
// __launch_bounds__(32, 1) releases ptxas's register cap (the R5 attempt at
// this layout spilled at 168 regs and regressed; ~210 are needed).
// Per step: stage uA,uB to double-buffered smem, ONE syncwarp, then the two
// matvecs interleave in a single basic block so each chain's stalls are
// filled by the other. x rows live in registers (shfl broadcast); softmax
// uses the D=2 logit difference (softplus), deferred one step.
__global__ void __launch_bounds__(32, 1) rnn2d_kernel(
    const int*   __restrict__ x,     // (B, 32, 32) int32, values in {0,1}
    const float* __restrict__ Win,   // (2, 64)
    const float* __restrict__ Wc,    // (64, 64)
    const float* __restrict__ bc,    // (64,)
    const float* __restrict__ Wout,  // (64, 2)
    const float* __restrict__ bout,  // (2,)
    float*       __restrict__ out)   // (B,)
{
    const int b0 = blockIdx.x * 2;
    const int t  = threadIdx.x;         // 0..31

    __shared__ float2 HprevA[LDIM][LDIM];            // [col][t] thread-private
    __shared__ float2 HprevB[LDIM][LDIM];
    __shared__ __align__(16) float ubufA[2][HDIM];   // double-buffered u
    __shared__ __align__(16) float ubufB[2][HDIM];

    // ---- shared weights: columns j0=t, j1=t+32 packed along k ----
    ull wcp0[HDIM / 2], wcp1[HDIM / 2];
#pragma unroll
    for (int k = 0; k < HDIM / 2; ++k) {
        wcp0[k] = pack2(Wc[(2 * k) * HDIM + t],      Wc[(2 * k + 1) * HDIM + t]);
        wcp1[k] = pack2(Wc[(2 * k) * HDIM + t + 32], Wc[(2 * k + 1) * HDIM + t + 32]);
    }
    const float win00 = Win[t],      win10 = Win[HDIM + t];
    const float win01 = Win[t + 32], win11 = Win[HDIM + t + 32];
    const float bc0   = bc[t],       bc1   = bc[t + 32];
    const float wod0  = Wout[t * 2]        - Wout[t * 2 + 1];
    const float wod1  = Wout[(t + 32) * 2] - Wout[(t + 32) * 2 + 1];
    const float bodt  = (t == 0) ? (bout[0] - bout[1]) : 0.0f;

#pragma unroll
    for (int c = 0; c < LDIM; ++c) {
        HprevA[c][t] = make_float2(0.0f, 0.0f);
        HprevB[c][t] = make_float2(0.0f, 0.0f);
    }

    const int* xbA = x + (size_t)b0 * LDIM * LDIM;
    const int* xbB = xbA + LDIM * LDIM;

    float logpA = 0.0f, logpB = 0.0f;
    float pdA = 0.0f,  pdB = 0.0f;      // deferred d-partials (d = z0 - z1)
    int   pxA = 0,     pxB = 0;
    float pend = 0.0f;
    float2 hpA = make_float2(0.0f, 0.0f);
    float2 hpB = make_float2(0.0f, 0.0f);

    int xvA = xbA[t], xvB = xbB[t];     // row 0
    int xvPrevA = 0,  xvPrevB = 0;

    for (int i = 0; i < LDIM; ++i) {
        const int rowN = (i < LDIM - 1) ? (i + 1) : (LDIM - 1);
        const int xvNextA = xbA[rowN * LDIM + t];
        const int xvNextB = xbB[rowN * LDIM + t];
        const int dir = (i & 1) ? -1 : 1;

        float hA0 = 0.0f, hA1 = 0.0f, hB0 = 0.0f, hB1 = 0.0f;
        int   xLA = 0, xLB = 0;

#pragma unroll 2
        for (int jj = 0; jj < LDIM; ++jj) {
            const int c = (i & 1) ? (LDIM - 1 - jj) : jj;
            const int p = jj & 1;

            // stage u for both samples (hp prefetched, thread-private)
            ubufA[p][t]      = hA0 + hpA.x;
            ubufA[p][t + 32] = hA1 + hpA.y;
            ubufB[p][t]      = hB0 + hpB.x;
            ubufB[p][t + 32] = hB1 + hpB.y;

            // base terms (register x, off the recurrence chain)
            float rA0 = bc0, rA1 = bc1, rB0 = bc0, rB1 = bc1;
            if (jj > 0) {
                rA0 += xLA ? win10 : win00;  rA1 += xLA ? win11 : win01;
                rB0 += xLB ? win10 : win00;  rB1 += xLB ? win11 : win01;
            }
            if (i > 0) {
                const int xUA = __shfl_sync(0xffffffffu, xvPrevA, c);
                const int xUB = __shfl_sync(0xffffffffu, xvPrevB, c);
                rA0 += xUA ? win10 : win00;  rA1 += xUA ? win11 : win01;
                rB0 += xUB ? win10 : win00;  rB1 += xUB ? win11 : win01;
            }

            __syncwarp();

            // ---- deferred softmax of step j-1, both samples (overlaps matvec) ----
            float dA = pdA, dB = pdB;
#pragma unroll
            for (int off = 16; off > 0; off >>= 1) {
                dA += __shfl_xor_sync(0xffffffffu, dA, off);
                dB += __shfl_xor_sync(0xffffffffu, dB, off);
            }
            {
                const float vA = pxA ? dA : -dA;
                const float vB = pxB ? dB : -dB;
                float lpA = -(fmaxf(vA, 0.0f) + __logf(1.0f + __expf(-fabsf(vA))));
                float lpB = -(fmaxf(vB, 0.0f) + __logf(1.0f + __expf(-fabsf(vB))));
                if (lpA != lpA) lpA = -35.0f;
                if (lpB != lpB) lpB = -35.0f;
                logpA += pend * lpA;
                logpB += pend * lpB;
            }

            // ---- two interleaved 64-wide matvecs over SHARED weight regs ----
            ull aA0 = pack2(rA0, 0.0f), aA1 = pack2(rA1, 0.0f);
            ull aB0 = pack2(rB0, 0.0f), aB1 = pack2(rB1, 0.0f);
            ull aA2 = 0, aA3 = 0, aB2 = 0, aB3 = 0;
            const ulonglong2* upA = (const ulonglong2*)ubufA[p];
            const ulonglong2* upB = (const ulonglong2*)ubufB[p];
#pragma unroll
            for (int k = 0; k < HDIM / 4; ++k) {
                const ulonglong2 uvA = upA[k];
                const ulonglong2 uvB = upB[k];
                FMA2(aA0, uvA.x, wcp0[2 * k],     aA0);
                FMA2(aB0, uvB.x, wcp0[2 * k],     aB0);
                FMA2(aA1, uvA.x, wcp1[2 * k],     aA1);
                FMA2(aB1, uvB.x, wcp1[2 * k],     aB1);
                FMA2(aA2, uvA.y, wcp0[2 * k + 1], aA2);
                FMA2(aB2, uvB.y, wcp0[2 * k + 1], aB2);
                FMA2(aA3, uvA.y, wcp1[2 * k + 1], aA3);
                FMA2(aB3, uvB.y, wcp1[2 * k + 1], aB3);
            }
            const float2 fA0 = unpack2(aA0), fA2 = unpack2(aA2);
            const float2 fA1 = unpack2(aA1), fA3 = unpack2(aA3);
            const float2 fB0 = unpack2(aB0), fB2 = unpack2(aB2);
            const float2 fB1 = unpack2(aB1), fB3 = unpack2(aB3);
            const float sA0 = (fA0.x + fA0.y) + (fA2.x + fA2.y);
            const float sA1 = (fA1.x + fA1.y) + (fA3.x + fA3.y);
            const float sB0 = (fB0.x + fB0.y) + (fB2.x + fB2.y);
            const float sB1 = (fB1.x + fB1.y) + (fB3.x + fB3.y);

            // elu (alpha = 1)
            const float nA0 = (sA0 > 0.0f) ? sA0 : (__expf(sA0) - 1.0f);
            const float nA1 = (sA1 > 0.0f) ? sA1 : (__expf(sA1) - 1.0f);
            const float nB0 = (sB0 > 0.0f) ? sB0 : (__expf(sB0) - 1.0f);
            const float nB1 = (sB1 > 0.0f) ? sB1 : (__expf(sB1) - 1.0f);

            // ---- stash this step's softmax inputs ----
            pxA  = __shfl_sync(0xffffffffu, xvA, c);
            pxB  = __shfl_sync(0xffffffffu, xvB, c);
            pdA  = nA0 * wod0 + nA1 * wod1 + bodt;
            pdB  = nB0 * wod0 + nB1 * wod1 + bodt;
            pend = 1.0f;

            // writeback + prefetch next carry-from-above (thread-private)
            HprevA[c][t] = make_float2(nA0, nA1);
            HprevB[c][t] = make_float2(nB0, nB1);
            const int cn = (jj < LDIM - 1) ? (c + dir) : c;
            hpA = HprevA[cn][t];
            hpB = HprevB[cn][t];

            hA0 = nA0; hA1 = nA1;
            hB0 = nB0; hB1 = nB1;
            xLA = pxA; xLB = pxB;
        }

        xvPrevA = xvA;  xvA = xvNextA;
        xvPrevB = xvB;  xvB = xvNextB;
    }

    // ---- flush the final pending step ----
    {
        float dA = pdA, dB = pdB;
#pragma unroll
        for (int off = 16; off > 0; off >>= 1) {
            dA += __shfl_xor_sync(0xffffffffu, dA, off);
            dB += __shfl_xor_sync(0xffffffffu, dB, off);
        }
        const float vA = pxA ? dA : -dA;
        const float vB = pxB ? dB : -dB;
        float lpA = -(fmaxf(vA, 0.0f) + __logf(1.0f + __expf(-fabsf(vA))));
        float lpB = -(fmaxf(vB, 0.0f) + __logf(1.0f + __expf(-fabsf(vB))));
        if (lpA != lpA) lpA = -35.0f;
        if (lpB != lpB) lpB = -35.0f;
        logpA += pend * lpA;
        logpB += pend * lpB;
    }

    if (t == 0) {
        out[b0]     = 0.5f * logpA;
        out[b0 + 1] = 0.5f * logpB;
    }
}

extern "C" void kernel_launch(void* const* d_in, const int* in_sizes, int n_in,
                              void* d_out, int out_size) {
    const int*   x    = (const int*)  d_in[0];
    const float* Win  = (const float*)d_in[1];
    const float* Wc   = (const float*)d_in[2];
    const float* bc   = (const float*)d_in[3];
    const float* Wout = (const float*)d_in[4];
    const float* bout = (const float*)d_in[5];
    float* out = (float*)d_out;

    const int B = in_sizes[0] / (LDIM * LDIM);
    rnn2d_kernel<<<B / 2, 32>>>(x, Win, Wc, bc, Wout, bout, out);
}